// round 9
// baseline (speedup 1.0000x reference)
#include <cuda_runtime.h>
#include <cuda_bf16.h>
#include <math.h>
#include <stdint.h>

// ---------------------------------------------------------------------------
// Problem constants
// ---------------------------------------------------------------------------
static constexpr int kN = 32;
static constexpr int kM = 32;
static constexpr int kP = 196;
static constexpr int kD = 768;
static constexpr float kMargin = 0.5f;
static constexpr float kEps = 1e-8f;

static constexpr int NN_PAIRS = kN * (kN - 1) / 2;      // 496
static constexpr int ND_PAIRS = kN * kM;                // 1024
static constexpr int TOTAL_PAIRS = NN_PAIRS + ND_PAIRS; // 1520

static constexpr int KC = 32;            // k-chunk in bf16 halves
static constexpr int NCHUNK = kD / KC;   // 24
static constexpr int STRIDE = 40;        // smem row stride in halves (80B: conflict-free ldmatrix)

// Dynamic smem layout (bytes)
static constexpr int A_BYTES   = 128 * STRIDE * 2;          // 10240 per buffer
static constexpr int B_BYTES   = 256 * STRIDE * 2;          // 20480 per buffer
static constexpr int OFF_A0    = 0;
static constexpr int OFF_A1    = OFF_A0 + A_BYTES;
static constexpr int OFF_B0    = OFF_A1 + A_BYTES;          // 20480
static constexpr int OFF_B1    = OFF_B0 + B_BYTES;          // 40960
static constexpr int OFF_PART  = OFF_B1 + B_BYTES;          // 61440: float[2][256]
static constexpr int OFF_CMAX  = OFF_PART + 2048;           // 63488: float[256]
static constexpr int OFF_RBUF  = OFF_CMAX + 1024;           // 64512: float[256]
static constexpr int SMEM_BYTES = OFF_RBUF + 1024;          // 65536

// Scratch (device globals — no allocations). 16B-aligned for vector access.
__device__ __align__(16) __nv_bfloat16 g_n1b[kN * kP * kD];
__device__ __align__(16) __nv_bfloat16 g_n2b[kM * kP * kD];
__device__ float g_pair_loss[TOTAL_PAIRS];

// ---------------------------------------------------------------------------
__device__ __forceinline__ uint32_t smem_u32(const void* p) {
    uint32_t a;
    asm("{ .reg .u64 t; cvta.to.shared.u64 t, %1; cvt.u32.u64 %0, t; }" : "=r"(a) : "l"(p));
    return a;
}

__device__ __forceinline__ void ldmatrix_x4(uint32_t& r0, uint32_t& r1,
                                            uint32_t& r2, uint32_t& r3, uint32_t addr) {
    asm volatile("ldmatrix.sync.aligned.m8n8.x4.shared.b16 {%0,%1,%2,%3}, [%4];"
                 : "=r"(r0), "=r"(r1), "=r"(r2), "=r"(r3) : "r"(addr));
}

__device__ __forceinline__ void mma_bf16(float* d, const uint32_t* a, uint32_t b0, uint32_t b1) {
    asm volatile(
        "mma.sync.aligned.m16n8k16.row.col.f32.bf16.bf16.f32 "
        "{%0,%1,%2,%3}, {%4,%5,%6,%7}, {%8,%9}, {%0,%1,%2,%3};"
        : "+f"(d[0]), "+f"(d[1]), "+f"(d[2]), "+f"(d[3])
        : "r"(a[0]), "r"(a[1]), "r"(a[2]), "r"(a[3]), "r"(b0), "r"(b1));
}

// cp.async 16B with zero-fill when invalid (src-size form)
__device__ __forceinline__ void cpa16(uint32_t dst, const void* src, bool valid) {
    int sz = valid ? 16 : 0;
    asm volatile("cp.async.cg.shared.global [%0], [%1], 16, %2;"
                 :: "r"(dst), "l"(src), "r"(sz) : "memory");
}
#define CPA_COMMIT() asm volatile("cp.async.commit_group;" ::: "memory")
#define CPA_WAIT0()  asm volatile("cp.async.wait_group 0;" ::: "memory")

// ---------------------------------------------------------------------------
// Kernel 1: row-wise L2 normalize, fp32 -> bf16
// ---------------------------------------------------------------------------
__global__ void normalize_kernel(const float* __restrict__ normal,
                                 const float* __restrict__ defect) {
    int row = blockIdx.x;
    const float* src;
    __nv_bfloat16* dst;
    if (row < kN * kP) {
        src = normal + (size_t)row * kD;
        dst = g_n1b + (size_t)row * kD;
    } else {
        int r = row - kN * kP;
        src = defect + (size_t)r * kD;
        dst = g_n2b + (size_t)r * kD;
    }
    int t = threadIdx.x;
    float v0 = src[t], v1 = src[t + 256], v2 = src[t + 512];
    float ss = v0 * v0 + v1 * v1 + v2 * v2;
    #pragma unroll
    for (int o = 16; o > 0; o >>= 1) ss += __shfl_xor_sync(0xffffffffu, ss, o);
    __shared__ float ws[8];
    __shared__ float s_scale;
    if ((t & 31) == 0) ws[t >> 5] = ss;
    __syncthreads();
    if (t == 0) {
        float tot = 0.f;
        #pragma unroll
        for (int w = 0; w < 8; w++) tot += ws[w];
        s_scale = 1.0f / (sqrtf(tot) + kEps);
    }
    __syncthreads();
    float s = s_scale;
    dst[t]       = __float2bfloat16(v0 * s);
    dst[t + 256] = __float2bfloat16(v1 * s);
    dst[t + 512] = __float2bfloat16(v2 * s);
}

// ---------------------------------------------------------------------------
__device__ __forceinline__ void decode_tri(int t, int& i, int& j) {
    float disc = (float)((2 * kN - 1) * (2 * kN - 1) - 8 * t);
    int ii = (int)((2.0f * kN - 1.0f - sqrtf(disc)) * 0.5f);
    while (ii > 0 && t < ii * (2 * kN - ii - 1) / 2) ii--;
    while (t >= (ii + 1) * (2 * kN - ii - 2) / 2 + (ii + 1)) ii++;
    int base = ii * (2 * kN - ii - 1) / 2;
    i = ii;
    j = ii + 1 + (t - base);
}

// ---------------------------------------------------------------------------
// Kernel 2: one CTA per pair. bf16 mma.sync GEMM + fused column-max + loss.
// Block covers 128(M) x 256(N) per pass, 2 M-passes. Warp grid 2(wy) x 4(wx),
// warp tile 64x64 (4 mt x 8 nt m16n8 frags). Padded 16x16 tiles skipped.
// ---------------------------------------------------------------------------
__global__ void __launch_bounds__(256, 1) pair_kernel() {
    extern __shared__ __align__(16) char sm[];
    float* s_part   = (float*)(sm + OFF_PART);   // [2][256]
    float* s_colmax = (float*)(sm + OFF_CMAX);   // [256]
    float* s_rbuf   = (float*)(sm + OFF_RBUF);   // [256]

    int tid = threadIdx.x;
    int lane = tid & 31;
    int wid = tid >> 5;
    int wy = wid >> 2;   // 0..1 -> M sub-block (64 rows)
    int wx = wid & 3;    // 0..3 -> N sub-block (64 cols)

    // Pair decode
    int pairIdx = blockIdx.x;
    const __nv_bfloat16* A;
    const __nv_bfloat16* B;
    bool is_nn;
    if (pairIdx < NN_PAIRS) {
        is_nn = true;
        int i, j;
        decode_tri(pairIdx, i, j);
        A = g_n1b + (size_t)i * kP * kD;
        B = g_n1b + (size_t)j * kP * kD;
    } else {
        is_nn = false;
        int t = pairIdx - NN_PAIRS;
        A = g_n1b + (size_t)(t / kM) * kP * kD;
        B = g_n2b + (size_t)(t % kM) * kP * kD;
    }

    s_colmax[tid] = -1e30f;
    __syncthreads();

    // cp.async staging: per chunk, A = 128 rows x 32h (512 x 16B), B = 256 rows (1024 x 16B)
    int ldRow = tid >> 2;               // 0..63
    int ldSeg = (tid & 3) * 8;          // halves offset within 32-half window

    uint32_t smA[2] = { smem_u32(sm + OFF_A0), smem_u32(sm + OFF_A1) };
    uint32_t smB[2] = { smem_u32(sm + OFF_B0), smem_u32(sm + OFF_B1) };
    uint32_t dstOff[4];
    #pragma unroll
    for (int it = 0; it < 4; it++)
        dstOff[it] = (uint32_t)(((ldRow + it * 64) * STRIDE + ldSeg) * 2);

    // ldmatrix lane addressing (byte offsets within a staging buffer)
    int ar = lane & 15, ah = lane >> 4;
    uint32_t aOffB = (uint32_t)(((wy * 64 + ar) * STRIDE + ah * 8) * 2);
    int bq = lane >> 3, brr = lane & 7;
    uint32_t bOffB = (uint32_t)(((wx * 64 + ((bq >> 1) & 1) * 8 + brr) * STRIDE + (bq & 1) * 8) * 2);

    // N-tile validity (uniform per warp): col base wx*64 + ntp*16 < kP
    bool nval[4];
    #pragma unroll
    for (int ntp = 0; ntp < 4; ntp++) nval[ntp] = (wx * 64 + ntp * 16) < kP;

    #pragma unroll 1
    for (int mb = 0; mb < 2; mb++) {
        int am0 = mb * 128;
        // M-tile validity (uniform per warp): row base am0 + wy*64 + mt*16 < kP
        bool mval[4];
        #pragma unroll
        for (int mt = 0; mt < 4; mt++) mval[mt] = (am0 + wy * 64 + mt * 16) < kP;

        float acc[4][8][4];
        #pragma unroll
        for (int mt = 0; mt < 4; mt++)
            #pragma unroll
            for (int nt = 0; nt < 8; nt++)
                #pragma unroll
                for (int e = 0; e < 4; e++) acc[mt][nt][e] = 0.0f;

        // Preload chunk 0 into buffer 0
        {
            #pragma unroll
            for (int it = 0; it < 2; it++) {
                int r = am0 + ldRow + it * 64;
                cpa16(smA[0] + dstOff[it], A + (size_t)r * kD + ldSeg, r < kP);
            }
            #pragma unroll
            for (int it = 0; it < 4; it++) {
                int r = ldRow + it * 64;
                cpa16(smB[0] + dstOff[it], B + (size_t)r * kD + ldSeg, r < kP);
            }
            CPA_COMMIT();
        }

        #pragma unroll 1
        for (int c = 0; c < NCHUNK; c++) {
            int b = c & 1;
            CPA_WAIT0();
            __syncthreads();   // buf c ready; all warps past mma(c-1)

            if (c + 1 < NCHUNK) {
                int nbuf = (c + 1) & 1;
                int k0 = (c + 1) * KC + ldSeg;
                #pragma unroll
                for (int it = 0; it < 2; it++) {
                    int r = am0 + ldRow + it * 64;
                    cpa16(smA[nbuf] + dstOff[it], A + (size_t)r * kD + k0, r < kP);
                }
                #pragma unroll
                for (int it = 0; it < 4; it++) {
                    int r = ldRow + it * 64;
                    cpa16(smB[nbuf] + dstOff[it], B + (size_t)r * kD + k0, r < kP);
                }
                CPA_COMMIT();
            }

            #pragma unroll
            for (int ks = 0; ks < 2; ks++) {
                uint32_t afr[4][4];
                #pragma unroll
                for (int mt = 0; mt < 4; mt++)
                    if (mval[mt])
                        ldmatrix_x4(afr[mt][0], afr[mt][1], afr[mt][2], afr[mt][3],
                                    smA[b] + aOffB + (uint32_t)((mt * 16 * STRIDE + ks * 16) * 2));
                #pragma unroll
                for (int ntp = 0; ntp < 4; ntp++) {
                    if (nval[ntp]) {
                        uint32_t b0, b1, b2, b3;
                        ldmatrix_x4(b0, b1, b2, b3,
                                    smB[b] + bOffB + (uint32_t)((ntp * 16 * STRIDE + ks * 16) * 2));
                        #pragma unroll
                        for (int mt = 0; mt < 4; mt++) {
                            if (mval[mt]) {
                                mma_bf16(acc[mt][ntp * 2 + 0], afr[mt], b0, b1);
                                mma_bf16(acc[mt][ntp * 2 + 1], afr[mt], b2, b3);
                            }
                        }
                    }
                }
            }
        }
        __syncthreads();   // all mma done before s_part reuse

        // ----- Epilogue: column max over this pass's valid rows -----
        #pragma unroll
        for (int nt = 0; nt < 8; nt++) {
            float c0 = -1e30f, c1 = -1e30f;
            #pragma unroll
            for (int mt = 0; mt < 4; mt++) {
                int r1 = am0 + wy * 64 + mt * 16 + (lane >> 2);
                bool v1 = r1 < kP, v2 = (r1 + 8) < kP;
                const float* cc = acc[mt][nt];
                c0 = fmaxf(c0, fmaxf(v1 ? cc[0] : -1e30f, v2 ? cc[2] : -1e30f));
                c1 = fmaxf(c1, fmaxf(v1 ? cc[1] : -1e30f, v2 ? cc[3] : -1e30f));
            }
            #pragma unroll
            for (int o = 4; o <= 16; o <<= 1) {
                c0 = fmaxf(c0, __shfl_xor_sync(0xffffffffu, c0, o));
                c1 = fmaxf(c1, __shfl_xor_sync(0xffffffffu, c1, o));
            }
            if (lane < 4) {
                int col = wx * 64 + nt * 8 + 2 * lane;
                s_part[wy * 256 + col]     = c0;
                s_part[wy * 256 + col + 1] = c1;
            }
        }
        __syncthreads();
        {
            float m = fmaxf(s_part[tid], s_part[256 + tid]);
            s_colmax[tid] = fmaxf(s_colmax[tid], m);
        }
        __syncthreads();
    }

    // ----- Loss over q < 196, block reduce -----
    float v = 0.0f;
    if (tid < kP) {
        float m = s_colmax[tid];
        v = is_nn ? (1.0f - m) : fmaxf(m - kMargin, 0.0f);
    }
    s_rbuf[tid] = v;
    __syncthreads();
    #pragma unroll
    for (int s = 128; s > 0; s >>= 1) {
        if (tid < s) s_rbuf[tid] += s_rbuf[tid + s];
        __syncthreads();
    }
    if (tid == 0) g_pair_loss[pairIdx] = s_rbuf[0];
}

// ---------------------------------------------------------------------------
// Kernel 3: deterministic finalize
// ---------------------------------------------------------------------------
__global__ void finalize_kernel(float* __restrict__ out) {
    int t = threadIdx.x;
    float pos = 0.f, neg = 0.f;
    for (int idx = t; idx < TOTAL_PAIRS; idx += 256) {
        float v = g_pair_loss[idx];
        if (idx < NN_PAIRS) pos += v; else neg += v;
    }
    #pragma unroll
    for (int o = 16; o > 0; o >>= 1) {
        pos += __shfl_xor_sync(0xffffffffu, pos, o);
        neg += __shfl_xor_sync(0xffffffffu, neg, o);
    }
    __shared__ float sp[8], sn[8];
    if ((t & 31) == 0) { sp[t >> 5] = pos; sn[t >> 5] = neg; }
    __syncthreads();
    if (t == 0) {
        float ptot = 0.f, ntot = 0.f;
        #pragma unroll
        for (int w = 0; w < 8; w++) { ptot += sp[w]; ntot += sn[w]; }
        out[0] = ptot / (float)(NN_PAIRS * kP) + ntot / (float)(kN * kM * kP);
    }
}

// ---------------------------------------------------------------------------
extern "C" void kernel_launch(void* const* d_in, const int* in_sizes, int n_in,
                              void* d_out, int out_size) {
    const float* normal = (const float*)d_in[0];
    const float* defect = (const float*)d_in[1];
    float* out = (float*)d_out;

    cudaFuncSetAttribute(pair_kernel, cudaFuncAttributeMaxDynamicSharedMemorySize, SMEM_BYTES);

    normalize_kernel<<<(kN + kM) * kP, 256>>>(normal, defect);
    pair_kernel<<<TOTAL_PAIRS, 256, SMEM_BYTES>>>();
    finalize_kernel<<<1, 256>>>(out);
}

// round 11
// speedup vs baseline: 1.0784x; 1.0784x over previous
#include <cuda_runtime.h>
#include <cuda_bf16.h>
#include <math.h>
#include <stdint.h>

// ---------------------------------------------------------------------------
// Problem constants
// ---------------------------------------------------------------------------
static constexpr int kN = 32;
static constexpr int kM = 32;
static constexpr int kP = 196;
static constexpr int kD = 768;
static constexpr float kMargin = 0.5f;
static constexpr float kEps = 1e-8f;

static constexpr int NN_PAIRS = kN * (kN - 1) / 2;      // 496
static constexpr int ND_PAIRS = kN * kM;                // 1024
static constexpr int TOTAL_PAIRS = NN_PAIRS + ND_PAIRS; // 1520

static constexpr int KC = 32;            // k-chunk in bf16 halves
static constexpr int NCHUNK = kD / KC;   // 24
static constexpr int STRIDE = 40;        // smem row stride in halves (80B: conflict-free ldmatrix)
static constexpr int STAGES = 3;

// Dynamic smem layout (bytes): 3-stage A/B staging + epilogue scratch
static constexpr int TILE_BYTES = 128 * STRIDE * 2;     // 10240 per stage (A or B)
static constexpr int OFF_A      = 0;                    // 3 stages
static constexpr int OFF_B      = OFF_A + STAGES * TILE_BYTES;   // 30720
static constexpr int OFF_PART   = OFF_B + STAGES * TILE_BYTES;   // 61440: float[4][128]
static constexpr int OFF_CMAX   = OFF_PART + 2048;               // 63488: float[256]
static constexpr int OFF_RBUF   = OFF_CMAX + 1024;               // 64512: float[256]
static constexpr int SMEM_BYTES = OFF_RBUF + 1024;               // 65536

// Scratch (device globals — no allocations). 16B-aligned for vector access.
__device__ __align__(16) __nv_bfloat16 g_n1b[kN * kP * kD];
__device__ __align__(16) __nv_bfloat16 g_n2b[kM * kP * kD];
__device__ float g_pair_loss[TOTAL_PAIRS];

// ---------------------------------------------------------------------------
__device__ __forceinline__ uint32_t smem_u32(const void* p) {
    uint32_t a;
    asm("{ .reg .u64 t; cvta.to.shared.u64 t, %1; cvt.u32.u64 %0, t; }" : "=r"(a) : "l"(p));
    return a;
}

__device__ __forceinline__ void ldmatrix_x4(uint32_t& r0, uint32_t& r1,
                                            uint32_t& r2, uint32_t& r3, uint32_t addr) {
    asm volatile("ldmatrix.sync.aligned.m8n8.x4.shared.b16 {%0,%1,%2,%3}, [%4];"
                 : "=r"(r0), "=r"(r1), "=r"(r2), "=r"(r3) : "r"(addr));
}

__device__ __forceinline__ void mma_bf16(float* d, const uint32_t* a, uint32_t b0, uint32_t b1) {
    asm volatile(
        "mma.sync.aligned.m16n8k16.row.col.f32.bf16.bf16.f32 "
        "{%0,%1,%2,%3}, {%4,%5,%6,%7}, {%8,%9}, {%0,%1,%2,%3};"
        : "+f"(d[0]), "+f"(d[1]), "+f"(d[2]), "+f"(d[3])
        : "r"(a[0]), "r"(a[1]), "r"(a[2]), "r"(a[3]), "r"(b0), "r"(b1));
}

// cp.async 16B with zero-fill when invalid (src-size form)
__device__ __forceinline__ void cpa16(uint32_t dst, const void* src, bool valid) {
    int sz = valid ? 16 : 0;
    asm volatile("cp.async.cg.shared.global [%0], [%1], 16, %2;"
                 :: "r"(dst), "l"(src), "r"(sz) : "memory");
}
#define CPA_COMMIT() asm volatile("cp.async.commit_group;" ::: "memory")
#define CPA_WAIT1()  asm volatile("cp.async.wait_group 1;" ::: "memory")

// ---------------------------------------------------------------------------
// Kernel 1: row-wise L2 normalize, fp32 -> bf16
// ---------------------------------------------------------------------------
__global__ void normalize_kernel(const float* __restrict__ normal,
                                 const float* __restrict__ defect) {
    int row = blockIdx.x;
    const float* src;
    __nv_bfloat16* dst;
    if (row < kN * kP) {
        src = normal + (size_t)row * kD;
        dst = g_n1b + (size_t)row * kD;
    } else {
        int r = row - kN * kP;
        src = defect + (size_t)r * kD;
        dst = g_n2b + (size_t)r * kD;
    }
    int t = threadIdx.x;
    float v0 = src[t], v1 = src[t + 256], v2 = src[t + 512];
    float ss = v0 * v0 + v1 * v1 + v2 * v2;
    #pragma unroll
    for (int o = 16; o > 0; o >>= 1) ss += __shfl_xor_sync(0xffffffffu, ss, o);
    __shared__ float ws[8];
    __shared__ float s_scale;
    if ((t & 31) == 0) ws[t >> 5] = ss;
    __syncthreads();
    if (t == 0) {
        float tot = 0.f;
        #pragma unroll
        for (int w = 0; w < 8; w++) tot += ws[w];
        s_scale = 1.0f / (sqrtf(tot) + kEps);
    }
    __syncthreads();
    float s = s_scale;
    dst[t]       = __float2bfloat16(v0 * s);
    dst[t + 256] = __float2bfloat16(v1 * s);
    dst[t + 512] = __float2bfloat16(v2 * s);
}

// ---------------------------------------------------------------------------
__device__ __forceinline__ void decode_tri(int t, int& i, int& j) {
    float disc = (float)((2 * kN - 1) * (2 * kN - 1) - 8 * t);
    int ii = (int)((2.0f * kN - 1.0f - sqrtf(disc)) * 0.5f);
    while (ii > 0 && t < ii * (2 * kN - ii - 1) / 2) ii--;
    while (t >= (ii + 1) * (2 * kN - ii - 2) / 2 + (ii + 1)) ii++;
    int base = ii * (2 * kN - ii - 1) / 2;
    i = ii;
    j = ii + 1 + (t - base);
}

// ---------------------------------------------------------------------------
// Kernel 2: one CTA per pair. bf16 mma.sync GEMM + fused column-max + loss.
// C blocks 128x128 (2x2 over padded 256); warp grid 4(M) x 2(N), warp tile
// 32x64 (2 mt x 8 nt frags). 16x16-granular skipping + 3-stage cp.async.
// ---------------------------------------------------------------------------
__global__ void __launch_bounds__(256, 2) pair_kernel() {
    extern __shared__ __align__(16) char sm[];
    float* s_part   = (float*)(sm + OFF_PART);   // [4][128]
    float* s_colmax = (float*)(sm + OFF_CMAX);   // [256]
    float* s_rbuf   = (float*)(sm + OFF_RBUF);   // [256]

    int tid = threadIdx.x;
    int lane = tid & 31;
    int wid = tid >> 5;
    int wy = wid >> 1;   // 0..3 -> M sub-block (32 rows)
    int wx = wid & 1;    // 0..1 -> N sub-block (64 cols)

    // Pair decode
    int pairIdx = blockIdx.x;
    const __nv_bfloat16* A;
    const __nv_bfloat16* B;
    bool is_nn;
    if (pairIdx < NN_PAIRS) {
        is_nn = true;
        int i, j;
        decode_tri(pairIdx, i, j);
        A = g_n1b + (size_t)i * kP * kD;
        B = g_n1b + (size_t)j * kP * kD;
    } else {
        is_nn = false;
        int t = pairIdx - NN_PAIRS;
        A = g_n1b + (size_t)(t / kM) * kP * kD;
        B = g_n2b + (size_t)(t % kM) * kP * kD;
    }

    s_colmax[tid] = -1e30f;
    __syncthreads();

    // cp.async staging: per chunk, A = 128 rows x 32h, B = 128 rows x 32h
    int ldRow0 = tid >> 2;              // 0..63
    int ldRow1 = ldRow0 + 64;           // 64..127
    int ldSeg  = (tid & 3) * 8;         // halves offset within 32-half window

    uint32_t smA[STAGES], smB[STAGES];
    #pragma unroll
    for (int s = 0; s < STAGES; s++) {
        smA[s] = smem_u32(sm + OFF_A + s * TILE_BYTES);
        smB[s] = smem_u32(sm + OFF_B + s * TILE_BYTES);
    }
    uint32_t dA0 = (uint32_t)((ldRow0 * STRIDE + ldSeg) * 2);
    uint32_t dA1 = (uint32_t)((ldRow1 * STRIDE + ldSeg) * 2);

    // ldmatrix lane addressing (byte offsets within a staging buffer)
    int ar = lane & 15, ah = lane >> 4;
    uint32_t aOffB = (uint32_t)(((wy * 32 + ar) * STRIDE + ah * 8) * 2);
    int bq = lane >> 3, brr = lane & 7;
    uint32_t bOffB = (uint32_t)(((wx * 64 + ((bq >> 1) & 1) * 8 + brr) * STRIDE + (bq & 1) * 8) * 2);

    #pragma unroll 1
    for (int mb = 0; mb < 2; mb++) {
        int am0 = mb * 128;
        // M-tile validity at 16-row granularity
        bool mval[2];
        #pragma unroll
        for (int mt = 0; mt < 2; mt++) mval[mt] = (am0 + wy * 32 + mt * 16) < kP;
        bool anyM = mval[0];   // mval[1] implies mval[0]

        #pragma unroll 1
        for (int nb = 0; nb < 2; nb++) {
            int bn0 = nb * 128;
            // N-tile validity at 16-col granularity
            bool nval[4];
            #pragma unroll
            for (int ntp = 0; ntp < 4; ntp++) nval[ntp] = (bn0 + wx * 64 + ntp * 16) < kP;

            float acc[2][8][4];
            #pragma unroll
            for (int mt = 0; mt < 2; mt++)
                #pragma unroll
                for (int nt = 0; nt < 8; nt++)
                    #pragma unroll
                    for (int e = 0; e < 4; e++) acc[mt][nt][e] = 0.0f;

            // Preload chunks 0 and 1 into stages 0 and 1
            #pragma unroll
            for (int pc = 0; pc < 2; pc++) {
                int k0 = pc * KC + ldSeg;
                int r0 = am0 + ldRow0, r1 = am0 + ldRow1;
                int s0 = bn0 + ldRow0, s1 = bn0 + ldRow1;
                cpa16(smA[pc] + dA0, A + (size_t)r0 * kD + k0, r0 < kP);
                cpa16(smA[pc] + dA1, A + (size_t)r1 * kD + k0, r1 < kP);
                cpa16(smB[pc] + dA0, B + (size_t)s0 * kD + k0, s0 < kP);
                cpa16(smB[pc] + dA1, B + (size_t)s1 * kD + k0, s1 < kP);
                CPA_COMMIT();
            }

            #pragma unroll 1
            for (int c = 0; c < NCHUNK; c++) {
                int b = c % STAGES;
                CPA_WAIT1();       // chunk c arrived (c+1 may still be in flight)
                __syncthreads();   // all warps past mma(c-1): stage (c+2)%3 reusable

                if (c + 2 < NCHUNK) {
                    int nbuf = (c + 2) % STAGES;
                    int k0 = (c + 2) * KC + ldSeg;
                    int r0 = am0 + ldRow0, r1 = am0 + ldRow1;
                    int s0 = bn0 + ldRow0, s1 = bn0 + ldRow1;
                    cpa16(smA[nbuf] + dA0, A + (size_t)r0 * kD + k0, r0 < kP);
                    cpa16(smA[nbuf] + dA1, A + (size_t)r1 * kD + k0, r1 < kP);
                    cpa16(smB[nbuf] + dA0, B + (size_t)s0 * kD + k0, s0 < kP);
                    cpa16(smB[nbuf] + dA1, B + (size_t)s1 * kD + k0, s1 < kP);
                }
                CPA_COMMIT();      // always commit (possibly empty) to keep group count sound

                if (anyM) {
                    #pragma unroll
                    for (int ks = 0; ks < 2; ks++) {
                        uint32_t a0[2][4];
                        #pragma unroll
                        for (int mt = 0; mt < 2; mt++)
                            if (mval[mt])
                                ldmatrix_x4(a0[mt][0], a0[mt][1], a0[mt][2], a0[mt][3],
                                            smA[b] + aOffB + (uint32_t)((mt * 16 * STRIDE + ks * 16) * 2));
                        #pragma unroll
                        for (int ntp = 0; ntp < 4; ntp++) {
                            if (nval[ntp]) {
                                uint32_t b0, b1, b2, b3;
                                ldmatrix_x4(b0, b1, b2, b3,
                                            smB[b] + bOffB + (uint32_t)((ntp * 16 * STRIDE + ks * 16) * 2));
                                #pragma unroll
                                for (int mt = 0; mt < 2; mt++) {
                                    if (mval[mt]) {
                                        mma_bf16(acc[mt][ntp * 2 + 0], a0[mt], b0, b1);
                                        mma_bf16(acc[mt][ntp * 2 + 1], a0[mt], b2, b3);
                                    }
                                }
                            }
                        }
                    }
                }
            }
            __syncthreads();   // all mma done before s_part reuse

            // ----- Epilogue: column max over this block's valid rows -----
            int rbase = am0 + wy * 32 + (lane >> 2);
            #pragma unroll
            for (int nt = 0; nt < 8; nt++) {
                float c0 = -1e30f, c1 = -1e30f;
                #pragma unroll
                for (int mt = 0; mt < 2; mt++) {
                    int r1 = rbase + mt * 16;
                    bool v1 = r1 < kP, v2 = (r1 + 8) < kP;
                    const float* cc = acc[mt][nt];
                    c0 = fmaxf(c0, fmaxf(v1 ? cc[0] : -1e30f, v2 ? cc[2] : -1e30f));
                    c1 = fmaxf(c1, fmaxf(v1 ? cc[1] : -1e30f, v2 ? cc[3] : -1e30f));
                }
                #pragma unroll
                for (int o = 4; o <= 16; o <<= 1) {
                    c0 = fmaxf(c0, __shfl_xor_sync(0xffffffffu, c0, o));
                    c1 = fmaxf(c1, __shfl_xor_sync(0xffffffffu, c1, o));
                }
                if (lane < 4) {
                    int col = wx * 64 + nt * 8 + 2 * lane;
                    s_part[wy * 128 + col]     = c0;
                    s_part[wy * 128 + col + 1] = c1;
                }
            }
            __syncthreads();
            if (tid < 128) {
                float m = fmaxf(fmaxf(s_part[0 * 128 + tid], s_part[1 * 128 + tid]),
                                fmaxf(s_part[2 * 128 + tid], s_part[3 * 128 + tid]));
                s_colmax[bn0 + tid] = fmaxf(s_colmax[bn0 + tid], m);
            }
            __syncthreads();
        }
    }

    // ----- Loss over q < 196, block reduce -----
    float v = 0.0f;
    if (tid < kP) {
        float m = s_colmax[tid];
        v = is_nn ? (1.0f - m) : fmaxf(m - kMargin, 0.0f);
    }
    s_rbuf[tid] = v;
    __syncthreads();
    #pragma unroll
    for (int s = 128; s > 0; s >>= 1) {
        if (tid < s) s_rbuf[tid] += s_rbuf[tid + s];
        __syncthreads();
    }
    if (tid == 0) g_pair_loss[pairIdx] = s_rbuf[0];
}

// ---------------------------------------------------------------------------
// Kernel 3: deterministic finalize
// ---------------------------------------------------------------------------
__global__ void finalize_kernel(float* __restrict__ out) {
    int t = threadIdx.x;
    float pos = 0.f, neg = 0.f;
    for (int idx = t; idx < TOTAL_PAIRS; idx += 256) {
        float v = g_pair_loss[idx];
        if (idx < NN_PAIRS) pos += v; else neg += v;
    }
    #pragma unroll
    for (int o = 16; o > 0; o >>= 1) {
        pos += __shfl_xor_sync(0xffffffffu, pos, o);
        neg += __shfl_xor_sync(0xffffffffu, neg, o);
    }
    __shared__ float sp[8], sn[8];
    if ((t & 31) == 0) { sp[t >> 5] = pos; sn[t >> 5] = neg; }
    __syncthreads();
    if (t == 0) {
        float ptot = 0.f, ntot = 0.f;
        #pragma unroll
        for (int w = 0; w < 8; w++) { ptot += sp[w]; ntot += sn[w]; }
        out[0] = ptot / (float)(NN_PAIRS * kP) + ntot / (float)(kN * kM * kP);
    }
}

// ---------------------------------------------------------------------------
extern "C" void kernel_launch(void* const* d_in, const int* in_sizes, int n_in,
                              void* d_out, int out_size) {
    const float* normal = (const float*)d_in[0];
    const float* defect = (const float*)d_in[1];
    float* out = (float*)d_out;

    cudaFuncSetAttribute(pair_kernel, cudaFuncAttributeMaxDynamicSharedMemorySize, SMEM_BYTES);

    normalize_kernel<<<(kN + kM) * kP, 256>>>(normal, defect);
    pair_kernel<<<TOTAL_PAIRS, 256, SMEM_BYTES>>>();
    finalize_kernel<<<1, 256>>>(out);
}

// round 12
// speedup vs baseline: 1.2512x; 1.1602x over previous
#include <cuda_runtime.h>
#include <cuda_bf16.h>
#include <math.h>
#include <stdint.h>

// ---------------------------------------------------------------------------
// Problem constants
// ---------------------------------------------------------------------------
static constexpr int kN = 32;
static constexpr int kM = 32;
static constexpr int kP = 196;
static constexpr int kD = 768;
static constexpr float kMargin = 0.5f;
static constexpr float kEps = 1e-8f;

static constexpr int NN_PAIRS = kN * (kN - 1) / 2;      // 496
static constexpr int ND_PAIRS = kN * kM;                // 1024
static constexpr int TOTAL_PAIRS = NN_PAIRS + ND_PAIRS; // 1520

static constexpr int KC = 64;            // k-chunk in bf16 halves (4 ks-steps)
static constexpr int NCHUNK = kD / KC;   // 12
static constexpr int STRIDE = 72;        // smem row stride in halves (144B: conflict-free ldmatrix)

// Dynamic smem layout (bytes): 2-stage A/B staging + epilogue scratch
static constexpr int TILE_BYTES = 128 * STRIDE * 2;              // 18432 per stage
static constexpr int OFF_A0     = 0;
static constexpr int OFF_A1     = OFF_A0 + TILE_BYTES;
static constexpr int OFF_B0     = OFF_A1 + TILE_BYTES;
static constexpr int OFF_B1     = OFF_B0 + TILE_BYTES;
static constexpr int OFF_PART   = OFF_B1 + TILE_BYTES;           // float[4][128]
static constexpr int OFF_CMAX   = OFF_PART + 2048;               // float[256]
static constexpr int OFF_RBUF   = OFF_CMAX + 1024;               // float[256]
static constexpr int SMEM_BYTES = OFF_RBUF + 1024;               // 77824

// Scratch (device globals — no allocations). 16B-aligned for vector access.
__device__ __align__(16) __nv_bfloat16 g_n1b[kN * kP * kD];
__device__ __align__(16) __nv_bfloat16 g_n2b[kM * kP * kD];
__device__ float g_pair_loss[TOTAL_PAIRS];

// ---------------------------------------------------------------------------
__device__ __forceinline__ uint32_t smem_u32(const void* p) {
    uint32_t a;
    asm("{ .reg .u64 t; cvta.to.shared.u64 t, %1; cvt.u32.u64 %0, t; }" : "=r"(a) : "l"(p));
    return a;
}

__device__ __forceinline__ void ldmatrix_x4(uint32_t& r0, uint32_t& r1,
                                            uint32_t& r2, uint32_t& r3, uint32_t addr) {
    asm volatile("ldmatrix.sync.aligned.m8n8.x4.shared.b16 {%0,%1,%2,%3}, [%4];"
                 : "=r"(r0), "=r"(r1), "=r"(r2), "=r"(r3) : "r"(addr));
}

__device__ __forceinline__ void mma_bf16(float* d, const uint32_t* a, uint32_t b0, uint32_t b1) {
    asm volatile(
        "mma.sync.aligned.m16n8k16.row.col.f32.bf16.bf16.f32 "
        "{%0,%1,%2,%3}, {%4,%5,%6,%7}, {%8,%9}, {%0,%1,%2,%3};"
        : "+f"(d[0]), "+f"(d[1]), "+f"(d[2]), "+f"(d[3])
        : "r"(a[0]), "r"(a[1]), "r"(a[2]), "r"(a[3]), "r"(b0), "r"(b1));
}

// cp.async 16B with zero-fill when invalid (src-size form)
__device__ __forceinline__ void cpa16(uint32_t dst, const void* src, bool valid) {
    int sz = valid ? 16 : 0;
    asm volatile("cp.async.cg.shared.global [%0], [%1], 16, %2;"
                 :: "r"(dst), "l"(src), "r"(sz) : "memory");
}
#define CPA_COMMIT() asm volatile("cp.async.commit_group;" ::: "memory")
#define CPA_WAIT0()  asm volatile("cp.async.wait_group 0;" ::: "memory")

// ---------------------------------------------------------------------------
// Kernel 1: row-wise L2 normalize, fp32 -> bf16
// ---------------------------------------------------------------------------
__global__ void normalize_kernel(const float* __restrict__ normal,
                                 const float* __restrict__ defect) {
    int row = blockIdx.x;
    const float* src;
    __nv_bfloat16* dst;
    if (row < kN * kP) {
        src = normal + (size_t)row * kD;
        dst = g_n1b + (size_t)row * kD;
    } else {
        int r = row - kN * kP;
        src = defect + (size_t)r * kD;
        dst = g_n2b + (size_t)r * kD;
    }
    int t = threadIdx.x;
    float v0 = src[t], v1 = src[t + 256], v2 = src[t + 512];
    float ss = v0 * v0 + v1 * v1 + v2 * v2;
    #pragma unroll
    for (int o = 16; o > 0; o >>= 1) ss += __shfl_xor_sync(0xffffffffu, ss, o);
    __shared__ float ws[8];
    __shared__ float s_scale;
    if ((t & 31) == 0) ws[t >> 5] = ss;
    __syncthreads();
    if (t == 0) {
        float tot = 0.f;
        #pragma unroll
        for (int w = 0; w < 8; w++) tot += ws[w];
        s_scale = 1.0f / (sqrtf(tot) + kEps);
    }
    __syncthreads();
    float s = s_scale;
    dst[t]       = __float2bfloat16(v0 * s);
    dst[t + 256] = __float2bfloat16(v1 * s);
    dst[t + 512] = __float2bfloat16(v2 * s);
}

// ---------------------------------------------------------------------------
__device__ __forceinline__ void decode_tri(int t, int& i, int& j) {
    float disc = (float)((2 * kN - 1) * (2 * kN - 1) - 8 * t);
    int ii = (int)((2.0f * kN - 1.0f - sqrtf(disc)) * 0.5f);
    while (ii > 0 && t < ii * (2 * kN - ii - 1) / 2) ii--;
    while (t >= (ii + 1) * (2 * kN - ii - 2) / 2 + (ii + 1)) ii++;
    int base = ii * (2 * kN - ii - 1) / 2;
    i = ii;
    j = ii + 1 + (t - base);
}

// ---------------------------------------------------------------------------
// Kernel 2: one CTA per pair. bf16 mma.sync GEMM + fused column-max + loss.
// C blocks 128x128 (2x2 over padded 256); warp grid 4(M) x 2(N), warp tile
// 32x64 (2 mt x 8 nt frags). KC=64 chunks (4 ks-steps per sync iteration).
// ---------------------------------------------------------------------------
__global__ void __launch_bounds__(256, 2) pair_kernel() {
    extern __shared__ __align__(16) char sm[];
    float* s_part   = (float*)(sm + OFF_PART);   // [4][128]
    float* s_colmax = (float*)(sm + OFF_CMAX);   // [256]
    float* s_rbuf   = (float*)(sm + OFF_RBUF);   // [256]

    int tid = threadIdx.x;
    int lane = tid & 31;
    int wid = tid >> 5;
    int wy = wid >> 1;   // 0..3 -> M sub-block (32 rows)
    int wx = wid & 1;    // 0..1 -> N sub-block (64 cols)

    // Pair decode
    int pairIdx = blockIdx.x;
    const __nv_bfloat16* A;
    const __nv_bfloat16* B;
    bool is_nn;
    if (pairIdx < NN_PAIRS) {
        is_nn = true;
        int i, j;
        decode_tri(pairIdx, i, j);
        A = g_n1b + (size_t)i * kP * kD;
        B = g_n1b + (size_t)j * kP * kD;
    } else {
        is_nn = false;
        int t = pairIdx - NN_PAIRS;
        A = g_n1b + (size_t)(t / kM) * kP * kD;
        B = g_n2b + (size_t)(t % kM) * kP * kD;
    }

    s_colmax[tid] = -1e30f;
    __syncthreads();

    // cp.async staging: per chunk, A/B = 128 rows x 64 halves = 1024 x 16B each.
    // Each thread: 4 A segs + 4 B segs. row base = tid>>3 (+32*it), seg = tid&7.
    int ldRowB = tid >> 3;              // 0..31
    int ldSeg  = (tid & 7) * 8;         // halves offset within 64-half window

    uint32_t smA[2] = { smem_u32(sm + OFF_A0), smem_u32(sm + OFF_A1) };
    uint32_t smB[2] = { smem_u32(sm + OFF_B0), smem_u32(sm + OFF_B1) };
    uint32_t dOff[4];
    #pragma unroll
    for (int it = 0; it < 4; it++)
        dOff[it] = (uint32_t)(((ldRowB + it * 32) * STRIDE + ldSeg) * 2);

    // ldmatrix lane addressing (byte offsets within a staging buffer)
    int ar = lane & 15, ah = lane >> 4;
    uint32_t aOffB = (uint32_t)(((wy * 32 + ar) * STRIDE + ah * 8) * 2);
    int bq = lane >> 3, brr = lane & 7;
    uint32_t bOffB = (uint32_t)(((wx * 64 + ((bq >> 1) & 1) * 8 + brr) * STRIDE + (bq & 1) * 8) * 2);

    #pragma unroll 1
    for (int mb = 0; mb < 2; mb++) {
        int am0 = mb * 128;
        // M-tile validity at 16-row granularity (uniform per warp)
        bool mval[2];
        #pragma unroll
        for (int mt = 0; mt < 2; mt++) mval[mt] = (am0 + wy * 32 + mt * 16) < kP;
        bool anyM = mval[0];

        #pragma unroll 1
        for (int nb = 0; nb < 2; nb++) {
            int bn0 = nb * 128;
            // N-tile validity at 16-col granularity (uniform per warp)
            bool nval[4];
            #pragma unroll
            for (int ntp = 0; ntp < 4; ntp++) nval[ntp] = (bn0 + wx * 64 + ntp * 16) < kP;

            float acc[2][8][4];
            #pragma unroll
            for (int mt = 0; mt < 2; mt++)
                #pragma unroll
                for (int nt = 0; nt < 8; nt++)
                    #pragma unroll
                    for (int e = 0; e < 4; e++) acc[mt][nt][e] = 0.0f;

            // Preload chunk 0 into buffer 0
            {
                #pragma unroll
                for (int it = 0; it < 4; it++) {
                    int r = am0 + ldRowB + it * 32;
                    cpa16(smA[0] + dOff[it], A + (size_t)r * kD + ldSeg, r < kP);
                }
                #pragma unroll
                for (int it = 0; it < 4; it++) {
                    int r = bn0 + ldRowB + it * 32;
                    cpa16(smB[0] + dOff[it], B + (size_t)r * kD + ldSeg, r < kP);
                }
                CPA_COMMIT();
            }

            #pragma unroll 1
            for (int c = 0; c < NCHUNK; c++) {
                int b = c & 1;
                CPA_WAIT0();
                __syncthreads();   // buf c ready; all warps past mma(c-1)

                if (c + 1 < NCHUNK) {
                    int nbuf = (c + 1) & 1;
                    int k0 = (c + 1) * KC + ldSeg;
                    #pragma unroll
                    for (int it = 0; it < 4; it++) {
                        int r = am0 + ldRowB + it * 32;
                        cpa16(smA[nbuf] + dOff[it], A + (size_t)r * kD + k0, r < kP);
                    }
                    #pragma unroll
                    for (int it = 0; it < 4; it++) {
                        int r = bn0 + ldRowB + it * 32;
                        cpa16(smB[nbuf] + dOff[it], B + (size_t)r * kD + k0, r < kP);
                    }
                    CPA_COMMIT();
                }

                if (anyM) {
                    #pragma unroll
                    for (int ks = 0; ks < 4; ks++) {
                        uint32_t a0[2][4];
                        #pragma unroll
                        for (int mt = 0; mt < 2; mt++)
                            if (mval[mt])
                                ldmatrix_x4(a0[mt][0], a0[mt][1], a0[mt][2], a0[mt][3],
                                            smA[b] + aOffB + (uint32_t)((mt * 16 * STRIDE + ks * 16) * 2));
                        #pragma unroll
                        for (int ntp = 0; ntp < 4; ntp++) {
                            if (nval[ntp]) {
                                uint32_t b0, b1, b2, b3;
                                ldmatrix_x4(b0, b1, b2, b3,
                                            smB[b] + bOffB + (uint32_t)((ntp * 16 * STRIDE + ks * 16) * 2));
                                #pragma unroll
                                for (int mt = 0; mt < 2; mt++) {
                                    if (mval[mt]) {
                                        mma_bf16(acc[mt][ntp * 2 + 0], a0[mt], b0, b1);
                                        mma_bf16(acc[mt][ntp * 2 + 1], a0[mt], b2, b3);
                                    }
                                }
                            }
                        }
                    }
                }
            }
            __syncthreads();   // all mma done before s_part reuse

            // ----- Epilogue: column max over this block's valid rows -----
            int rbase = am0 + wy * 32 + (lane >> 2);
            #pragma unroll
            for (int nt = 0; nt < 8; nt++) {
                float c0 = -1e30f, c1 = -1e30f;
                #pragma unroll
                for (int mt = 0; mt < 2; mt++) {
                    int r1 = rbase + mt * 16;
                    bool v1 = r1 < kP, v2 = (r1 + 8) < kP;
                    const float* cc = acc[mt][nt];
                    c0 = fmaxf(c0, fmaxf(v1 ? cc[0] : -1e30f, v2 ? cc[2] : -1e30f));
                    c1 = fmaxf(c1, fmaxf(v1 ? cc[1] : -1e30f, v2 ? cc[3] : -1e30f));
                }
                #pragma unroll
                for (int o = 4; o <= 16; o <<= 1) {
                    c0 = fmaxf(c0, __shfl_xor_sync(0xffffffffu, c0, o));
                    c1 = fmaxf(c1, __shfl_xor_sync(0xffffffffu, c1, o));
                }
                if (lane < 4) {
                    int col = wx * 64 + nt * 8 + 2 * lane;
                    s_part[wy * 128 + col]     = c0;
                    s_part[wy * 128 + col + 1] = c1;
                }
            }
            __syncthreads();
            if (tid < 128) {
                float m = fmaxf(fmaxf(s_part[0 * 128 + tid], s_part[1 * 128 + tid]),
                                fmaxf(s_part[2 * 128 + tid], s_part[3 * 128 + tid]));
                s_colmax[bn0 + tid] = fmaxf(s_colmax[bn0 + tid], m);
            }
            __syncthreads();
        }
    }

    // ----- Loss over q < 196, block reduce -----
    float v = 0.0f;
    if (tid < kP) {
        float m = s_colmax[tid];
        v = is_nn ? (1.0f - m) : fmaxf(m - kMargin, 0.0f);
    }
    s_rbuf[tid] = v;
    __syncthreads();
    #pragma unroll
    for (int s = 128; s > 0; s >>= 1) {
        if (tid < s) s_rbuf[tid] += s_rbuf[tid + s];
        __syncthreads();
    }
    if (tid == 0) g_pair_loss[pairIdx] = s_rbuf[0];
}

// ---------------------------------------------------------------------------
// Kernel 3: deterministic finalize
// ---------------------------------------------------------------------------
__global__ void finalize_kernel(float* __restrict__ out) {
    int t = threadIdx.x;
    float pos = 0.f, neg = 0.f;
    for (int idx = t; idx < TOTAL_PAIRS; idx += 256) {
        float v = g_pair_loss[idx];
        if (idx < NN_PAIRS) pos += v; else neg += v;
    }
    #pragma unroll
    for (int o = 16; o > 0; o >>= 1) {
        pos += __shfl_xor_sync(0xffffffffu, pos, o);
        neg += __shfl_xor_sync(0xffffffffu, neg, o);
    }
    __shared__ float sp[8], sn[8];
    if ((t & 31) == 0) { sp[t >> 5] = pos; sn[t >> 5] = neg; }
    __syncthreads();
    if (t == 0) {
        float ptot = 0.f, ntot = 0.f;
        #pragma unroll
        for (int w = 0; w < 8; w++) { ptot += sp[w]; ntot += sn[w]; }
        out[0] = ptot / (float)(NN_PAIRS * kP) + ntot / (float)(kN * kM * kP);
    }
}

// ---------------------------------------------------------------------------
extern "C" void kernel_launch(void* const* d_in, const int* in_sizes, int n_in,
                              void* d_out, int out_size) {
    const float* normal = (const float*)d_in[0];
    const float* defect = (const float*)d_in[1];
    float* out = (float*)d_out;

    cudaFuncSetAttribute(pair_kernel, cudaFuncAttributeMaxDynamicSharedMemorySize, SMEM_BYTES);

    normalize_kernel<<<(kN + kM) * kP, 256>>>(normal, defect);
    pair_kernel<<<TOTAL_PAIRS, 256, SMEM_BYTES>>>();
    finalize_kernel<<<1, 256>>>(out);
}